// round 11
// baseline (speedup 1.0000x reference)
// MultiHead fused block: bf16x3 mma.sync + cp.async pipelines.
// R11: GEMM BK=32, double-buffered (2x40KB stages), half the barriers,
// 96 MMAs per warp between syncs. Attention unchanged from R9/R10.
#include <cuda_runtime.h>
#include <cuda_bf16.h>

#define Bb 2
#define Ss 2048
#define Ee 1024
#define Hh 16
#define Dd 64
#define Mrows (Bb*Ss)
#define NHD ((size_t)Bb*Hh*Ss*Dd)

__device__ __nv_bfloat16 cA_h[3*(size_t)Mrows*Ee], cA_l[3*(size_t)Mrows*Ee];
__device__ __nv_bfloat16 cW_h[4*(size_t)Ee*Ee],    cW_l[4*(size_t)Ee*Ee];
__device__ __nv_bfloat16 g_qh_h[NHD], g_qh_l[NHD];   // [B,H,S,D], pre-scaled
__device__ __nv_bfloat16 g_kh_h[NHD], g_kh_l[NHD];   // [B,H,S,D]
__device__ __nv_bfloat16 g_vt_h[NHD], g_vt_l[NHD];   // [B,H,D,S]
__device__ __nv_bfloat16 g_ao_h[(size_t)Mrows*Ee], g_ao_l[(size_t)Mrows*Ee];

__device__ __forceinline__ unsigned smem_u32(const void* p){
    unsigned a;
    asm("{ .reg .u64 t; cvta.to.shared.u64 t, %1; cvt.u32.u64 %0, t; }"
        : "=r"(a) : "l"(p));
    return a;
}
__device__ __forceinline__ unsigned packbf(float e0, float e1){
    unsigned r;   // lo half = e0, hi half = e1
    asm("cvt.rn.bf16x2.f32 %0, %1, %2;" : "=r"(r) : "f"(e1), "f"(e0));
    return r;
}
__device__ __forceinline__ float bferr(float x){
    __nv_bfloat16 h = __float2bfloat16(x);
    return x - __bfloat162float(h);
}
__device__ __forceinline__ void mma16816(float* d, const unsigned* a, const unsigned* b){
    asm volatile(
        "mma.sync.aligned.m16n8k16.row.col.f32.bf16.bf16.f32 "
        "{%0,%1,%2,%3}, {%4,%5,%6,%7}, {%8,%9}, {%0,%1,%2,%3};"
        : "+f"(d[0]), "+f"(d[1]), "+f"(d[2]), "+f"(d[3])
        : "r"(a[0]), "r"(a[1]), "r"(a[2]), "r"(a[3]), "r"(b[0]), "r"(b[1]));
}
__device__ __forceinline__ void ldsm4(unsigned addr, unsigned* r){
    asm volatile("ldmatrix.sync.aligned.m8n8.x4.shared.b16 {%0,%1,%2,%3}, [%4];"
                 : "=r"(r[0]), "=r"(r[1]), "=r"(r[2]), "=r"(r[3]) : "r"(addr));
}
__device__ __forceinline__ void cp16(unsigned dst, const void* src){
    asm volatile("cp.async.cg.shared.global [%0], [%1], 16;"
                 :: "r"(dst), "l"(__cvta_generic_to_global(src)) : "memory");
}
#define CP_COMMIT() asm volatile("cp.async.commit_group;" ::: "memory")
#define CP_WAIT(n)  asm volatile("cp.async.wait_group %0;" :: "n"(n) : "memory")

// ---------------------------------------------------------------------------
// Convert fp32 -> bf16 hi/lo planes. z=0..2 inputs, z=3..6 weights.
// ---------------------------------------------------------------------------
__global__ __launch_bounds__(256) void conv_hilo(
    const float* __restrict__ q, const float* __restrict__ k,
    const float* __restrict__ v,
    const float* __restrict__ Wq, const float* __restrict__ Wk,
    const float* __restrict__ Wv, const float* __restrict__ Wo)
{
    const int z = blockIdx.z;
    const float* src; __nv_bfloat16 *dh, *dl; size_t n;
    if (z < 3) {
        src = (z == 0) ? q : (z == 1) ? k : v;
        dh = cA_h + (size_t)z * Mrows * Ee;
        dl = cA_l + (size_t)z * Mrows * Ee;
        n = (size_t)Mrows * Ee;
    } else {
        src = (z == 3) ? Wq : (z == 4) ? Wk : (z == 5) ? Wv : Wo;
        dh = cW_h + (size_t)(z - 3) * Ee * Ee;
        dl = cW_l + (size_t)(z - 3) * Ee * Ee;
        n = (size_t)Ee * Ee;
    }
    size_t i = ((size_t)blockIdx.x * 256 + threadIdx.x) * 4;
    if (i >= n) return;
    float4 x = *(const float4*)(src + i);
    *(unsigned*)&dh[i]   = packbf(x.x, x.y);
    *(unsigned*)&dh[i+2] = packbf(x.z, x.w);
    *(unsigned*)&dl[i]   = packbf(bferr(x.x), bferr(x.y));
    *(unsigned*)&dl[i+2] = packbf(bferr(x.z), bferr(x.w));
}

// ---------------------------------------------------------------------------
// GEMM core: 128x128 CTA, BK=32, 2-buffer cp.async, 256 thr, 8 warps (4m x 2n),
// warp tile 32x64, bf16x3. Smem: 4 planes x 128 rows x 80B stride (64B data).
// ---------------------------------------------------------------------------
#define GPL 10240              // plane: 128 * 80
#define GST (4*GPL)            // stage: 40960
#define GE_DYN (2*GST)         // 81920

__device__ __forceinline__ void gemm_tc(float acc[2][8][4],
        const __nv_bfloat16* __restrict__ Agh, const __nv_bfloat16* __restrict__ Agl,
        const __nv_bfloat16* __restrict__ Bgh, const __nv_bfloat16* __restrict__ Bgl,
        unsigned sbase, int tid)
{
    const int lane = tid & 31, wid = tid >> 5;
    const int wm = (wid & 3) * 32, wn = (wid >> 2) * 64;

    const int r = tid >> 1, ch = tid & 1;      // row 0..127, 32B col half
    const __nv_bfloat16* pAh = Agh + (size_t)r * Ee + ch * 16;
    const __nv_bfloat16* pAl = Agl + (size_t)r * Ee + ch * 16;
    const __nv_bfloat16* pBh = Bgh + (size_t)r * Ee + ch * 16;
    const __nv_bfloat16* pBl = Bgl + (size_t)r * Ee + ch * 16;
    const unsigned drow = (unsigned)(r * 80 + ch * 32);

    unsigned aoff[2];
    #pragma unroll
    for (int mt = 0; mt < 2; mt++) {
        int row = wm + mt*16 + ((lane>>3)&1)*8 + (lane&7);
        aoff[mt] = (unsigned)(row*80 + ((lane>>4)<<4));
    }
    unsigned boff[4];
    #pragma unroll
    for (int np = 0; np < 4; np++) {
        int row = wn + np*16 + ((lane>>4)&1)*8 + (lane&7);
        boff[np] = (unsigned)(row*80 + (((lane>>3)&1)<<4));
    }

    // prologue: stage 0
    {
        unsigned sb = sbase;
        cp16(sb + drow,              pAh);
        cp16(sb + drow + 16,         pAh + 8);
        cp16(sb + GPL + drow,        pAl);
        cp16(sb + GPL + drow + 16,   pAl + 8);
        cp16(sb + 2*GPL + drow,      pBh);
        cp16(sb + 2*GPL + drow + 16, pBh + 8);
        cp16(sb + 3*GPL + drow,      pBl);
        cp16(sb + 3*GPL + drow + 16, pBl + 8);
        CP_COMMIT();
    }

    for (int s = 0; s < Ee/32; s++) {
        CP_WAIT(0);
        __syncthreads();
        const unsigned sb = sbase + (unsigned)(s & 1) * GST;

        if (s + 1 < Ee/32) {
            const int k0 = (s + 1) * 32;
            unsigned sb2 = sbase + (unsigned)((s + 1) & 1) * GST;
            cp16(sb2 + drow,              pAh + k0);
            cp16(sb2 + drow + 16,         pAh + k0 + 8);
            cp16(sb2 + GPL + drow,        pAl + k0);
            cp16(sb2 + GPL + drow + 16,   pAl + k0 + 8);
            cp16(sb2 + 2*GPL + drow,      pBh + k0);
            cp16(sb2 + 2*GPL + drow + 16, pBh + k0 + 8);
            cp16(sb2 + 3*GPL + drow,      pBl + k0);
            cp16(sb2 + 3*GPL + drow + 16, pBl + k0 + 8);
        }
        CP_COMMIT();

        #pragma unroll
        for (int kh = 0; kh < 2; kh++) {
            const unsigned kob = kh * 32;
            unsigned ah[2][4], al[2][4];
            ldsm4(sb + aoff[0] + kob, ah[0]);  ldsm4(sb + GPL + aoff[0] + kob, al[0]);
            ldsm4(sb + aoff[1] + kob, ah[1]);  ldsm4(sb + GPL + aoff[1] + kob, al[1]);
            #pragma unroll
            for (int np = 0; np < 4; np++) {
                unsigned bh[4], bl[4];
                ldsm4(sb + 2*GPL + boff[np] + kob, bh);
                ldsm4(sb + 3*GPL + boff[np] + kob, bl);
                #pragma unroll
                for (int pl = 0; pl < 3; pl++) {
                    const unsigned* a0 = (pl == 2) ? al[0] : ah[0];
                    const unsigned* a1 = (pl == 2) ? al[1] : ah[1];
                    const unsigned* bb = (pl == 1) ? bl : bh;
                    #pragma unroll
                    for (int hf = 0; hf < 2; hf++) {
                        mma16816(acc[0][np*2+hf], a0, bb + hf*2);
                        mma16816(acc[1][np*2+hf], a1, bb + hf*2);
                    }
                }
            }
        }
    }
}

// ---------------------------------------------------------------------------
// QKV projection; writes bf16 hi/lo planes (Q pre-scaled by 0.125*log2e).
// ---------------------------------------------------------------------------
__global__ __launch_bounds__(256, 2) void qkv_mma(
    const float* __restrict__ bq, const float* __restrict__ bk,
    const float* __restrict__ bv)
{
    extern __shared__ char smraw[];
    unsigned sbase = smem_u32(smraw);
    const int tid = threadIdx.x;
    const int z = blockIdx.z;
    const int m0 = blockIdx.y * 128, n0 = blockIdx.x * 128;
    const float* bias = (z == 0) ? bq : (z == 1) ? bk : bv;

    float acc[2][8][4] = {};
    gemm_tc(acc,
            cA_h + ((size_t)z*Mrows + m0)*Ee, cA_l + ((size_t)z*Mrows + m0)*Ee,
            cW_h + ((size_t)z*Ee + n0)*Ee,    cW_l + ((size_t)z*Ee + n0)*Ee,
            sbase, tid);

    const int lane = tid & 31, wid = tid >> 5;
    const int g = lane >> 2, t = lane & 3;
    const int wm = (wid & 3) * 32, wn = (wid >> 2) * 64;
    const float QSCALE = 0.125f * 1.4426950408889634f;

    #pragma unroll
    for (int mt = 0; mt < 2; mt++) {
        #pragma unroll
        for (int nt = 0; nt < 8; nt++) {
            int m = m0 + wm + mt*16 + g;
            int n = n0 + wn + nt*8 + t*2;
            float b0v = bias[n], b1v = bias[n+1];
            int b = m >> 11, s = m & 2047;
            int h = n >> 6, d = n & 63;
            float v00 = acc[mt][nt][0] + b0v, v01 = acc[mt][nt][1] + b1v;
            float v10 = acc[mt][nt][2] + b0v, v11 = acc[mt][nt][3] + b1v;
            if (z == 0) {
                v00 *= QSCALE; v01 *= QSCALE; v10 *= QSCALE; v11 *= QSCALE;
                size_t i0 = (((size_t)(b*Hh + h))*Ss + s)*Dd + d;
                *(unsigned*)&g_qh_h[i0] = packbf(v00, v01);
                *(unsigned*)&g_qh_l[i0] = packbf(bferr(v00), bferr(v01));
                size_t i1 = i0 + 8*Dd;
                *(unsigned*)&g_qh_h[i1] = packbf(v10, v11);
                *(unsigned*)&g_qh_l[i1] = packbf(bferr(v10), bferr(v11));
            } else if (z == 1) {
                size_t i0 = (((size_t)(b*Hh + h))*Ss + s)*Dd + d;
                *(unsigned*)&g_kh_h[i0] = packbf(v00, v01);
                *(unsigned*)&g_kh_l[i0] = packbf(bferr(v00), bferr(v01));
                size_t i1 = i0 + 8*Dd;
                *(unsigned*)&g_kh_h[i1] = packbf(v10, v11);
                *(unsigned*)&g_kh_l[i1] = packbf(bferr(v10), bferr(v11));
            } else {
                size_t i0 = (((size_t)(b*Hh + h))*Dd + d)*Ss + s;
                g_vt_h[i0]      = __float2bfloat16(v00);
                g_vt_l[i0]      = __float2bfloat16(bferr(v00));
                g_vt_h[i0+Ss]   = __float2bfloat16(v01);
                g_vt_l[i0+Ss]   = __float2bfloat16(bferr(v01));
                g_vt_h[i0+8]    = __float2bfloat16(v10);
                g_vt_l[i0+8]    = __float2bfloat16(bferr(v10));
                g_vt_h[i0+Ss+8] = __float2bfloat16(v11);
                g_vt_l[i0+Ss+8] = __float2bfloat16(bferr(v11));
            }
        }
    }
}

// ---------------------------------------------------------------------------
// Output projection + bias + residual (fp32 out)
// ---------------------------------------------------------------------------
__global__ __launch_bounds__(256, 2) void oproj_mma(
    const float* __restrict__ qin, const float* __restrict__ bo,
    float* __restrict__ out)
{
    extern __shared__ char smraw[];
    unsigned sbase = smem_u32(smraw);
    const int tid = threadIdx.x;
    const int m0 = blockIdx.y * 128, n0 = blockIdx.x * 128;

    float acc[2][8][4] = {};
    gemm_tc(acc,
            g_ao_h + (size_t)m0*Ee, g_ao_l + (size_t)m0*Ee,
            cW_h + ((size_t)3*Ee + n0)*Ee, cW_l + ((size_t)3*Ee + n0)*Ee,
            sbase, tid);

    const int lane = tid & 31, wid = tid >> 5;
    const int g = lane >> 2, t = lane & 3;
    const int wm = (wid & 3) * 32, wn = (wid >> 2) * 64;

    #pragma unroll
    for (int mt = 0; mt < 2; mt++) {
        #pragma unroll
        for (int nt = 0; nt < 8; nt++) {
            int m = m0 + wm + mt*16 + g;
            int n = n0 + wn + nt*8 + t*2;
            float b0v = bo[n], b1v = bo[n+1];
            size_t i0 = (size_t)m * Ee + n;
            size_t i1 = (size_t)(m+8) * Ee + n;
            out[i0]   = acc[mt][nt][0] + b0v + qin[i0];
            out[i0+1] = acc[mt][nt][1] + b1v + qin[i0+1];
            out[i1]   = acc[mt][nt][2] + b0v + qin[i1];
            out[i1+1] = acc[mt][nt][3] + b1v + qin[i1+1];
        }
    }
}

// ---------------------------------------------------------------------------
// Flash attention: 3-stage cp.async K/V pipeline, no-max softmax, bf16x3.
// Unchanged from R9/R10.
// ---------------------------------------------------------------------------
#define APL 9216
#define AST (4*APL)
#define AMSK (3*AST)
#define AT_DYN (AMSK + 2048)

__global__ __launch_bounds__(256, 1) void attn_mma(const unsigned char* __restrict__ mask)
{
    extern __shared__ char smraw[];
    unsigned sbase = smem_u32(smraw);
    const int tid = threadIdx.x;
    const int lane = tid & 31, w = tid >> 5;
    const int g = lane >> 2, t = lane & 3;
    const int bh = blockIdx.y, b = bh >> 4, h = bh & 15;
    const int q0 = blockIdx.x * 128;

    ((unsigned long long*)(smraw + AMSK))[tid] =
        ((const unsigned long long*)(mask + (size_t)b * Ss))[tid];

    {
        const __nv_bfloat16* Qh = g_qh_h + ((size_t)bh * Ss + q0) * Dd;
        const __nv_bfloat16* Ql = g_qh_l + ((size_t)bh * Ss + q0) * Dd;
        const int qr = tid >> 1;
        const int qc = (tid & 1) * 4;
        const unsigned hiplane = (qr >= 64) ? (unsigned)APL : 0u;
        unsigned qdst = sbase + hiplane + (unsigned)((qr & 63) * 144 + qc * 16);
        #pragma unroll
        for (int i = 0; i < 4; i++) {
            cp16(qdst + i*16,         Qh + (size_t)qr*64 + (qc+i)*8);
            cp16(qdst + 2*APL + i*16, Ql + (size_t)qr*64 + (qc+i)*8);
        }
        CP_COMMIT();
        CP_WAIT(0);
        __syncthreads();
    }

    unsigned qfh[4][4], qfl[4][4];
    {
        const int rowfull = w*16 + ((lane>>3)&1)*8 + (lane&7);
        const unsigned hiplane = (rowfull >= 64) ? (unsigned)APL : 0u;
        const unsigned off = hiplane + (unsigned)(((rowfull & 63)*36 + ((lane>>4)<<2)) * 4);
        #pragma unroll
        for (int dt = 0; dt < 4; dt++) {
            ldsm4(sbase + off + dt*32,         qfh[dt]);
            ldsm4(sbase + 2*APL + off + dt*32, qfl[dt]);
        }
    }
    __syncthreads();

    const __nv_bfloat16* Kh_g = g_kh_h + (size_t)bh * Ss * Dd;
    const __nv_bfloat16* Kl_g = g_kh_l + (size_t)bh * Ss * Dd;
    const __nv_bfloat16* Vh_g = g_vt_h + (size_t)bh * Dd * Ss;
    const __nv_bfloat16* Vl_g = g_vt_l + (size_t)bh * Dd * Ss;

    const int r2 = tid >> 2;
    const int cb = (tid & 3) * 2;
    const unsigned drow = (unsigned)(r2 * 144 + cb * 16);
    const __nv_bfloat16* pKh = Kh_g + (size_t)r2 * Dd + cb * 8;
    const __nv_bfloat16* pKl = Kl_g + (size_t)r2 * Dd + cb * 8;
    const __nv_bfloat16* pVh = Vh_g + (size_t)r2 * Ss + cb * 8;
    const __nv_bfloat16* pVl = Vl_g + (size_t)r2 * Ss + cb * 8;

    #pragma unroll
    for (int st = 0; st < 2; st++) {
        unsigned sb = sbase + st*AST;
        #pragma unroll
        for (int i = 0; i < 2; i++) {
            cp16(sb + drow + i*16,         pKh + (size_t)st*64*Dd + i*8);
            cp16(sb + APL + drow + i*16,   pKl + (size_t)st*64*Dd + i*8);
            cp16(sb + 2*APL + drow + i*16, pVh + st*64 + i*8);
            cp16(sb + 3*APL + drow + i*16, pVl + st*64 + i*8);
        }
        CP_COMMIT();
    }

    unsigned kvoff[4];
    #pragma unroll
    for (int np = 0; np < 4; np++) {
        int row = np*16 + ((lane>>4)&1)*8 + (lane&7);
        kvoff[np] = (unsigned)((row*36 + (((lane>>3)&1)<<2)) * 4);
    }

    const unsigned char* mb = (const unsigned char*)(smraw + AMSK);
    float O[8][4] = {};
    float l0 = 0.f, l1 = 0.f;

    for (int kt = 0; kt < Ss/64; kt++) {
        CP_WAIT(1);
        __syncthreads();
        const unsigned sb = sbase + (unsigned)(kt % 3) * AST;

        float Sc[8][4] = {};
        #pragma unroll
        for (int dt = 0; dt < 4; dt++) {
            const unsigned kob = dt*32;
            #pragma unroll
            for (int pp = 0; pp < 2; pp++) {
                unsigned kbh0[4], kbl0[4], kbh1[4], kbl1[4];
                ldsm4(sb + kvoff[pp*2]   + kob, kbh0);
                ldsm4(sb + APL + kvoff[pp*2]   + kob, kbl0);
                ldsm4(sb + kvoff[pp*2+1] + kob, kbh1);
                ldsm4(sb + APL + kvoff[pp*2+1] + kob, kbl1);
                #pragma unroll
                for (int pl = 0; pl < 3; pl++) {
                    const unsigned* aq = (pl == 2) ? qfl[dt] : qfh[dt];
                    const unsigned* b0 = (pl == 1) ? kbl0 : kbh0;
                    const unsigned* b1 = (pl == 1) ? kbl1 : kbh1;
                    #pragma unroll
                    for (int hf = 0; hf < 2; hf++) {
                        mma16816(Sc[pp*4 + hf],     aq, b0 + hf*2);
                        mma16816(Sc[pp*4 + 2 + hf], aq, b1 + hf*2);
                    }
                }
            }
        }

        unsigned pah[4][4], pal[4][4];
        #pragma unroll
        for (int nt = 0; nt < 8; nt++) {
            int j = kt*64 + nt*8 + t*2;
            float mv0 = mb[j]   ? -1e9f : 0.f;
            float mv1 = mb[j+1] ? -1e9f : 0.f;
            float p0 = exp2f(Sc[nt][0] + mv0);
            float p1 = exp2f(Sc[nt][1] + mv1);
            float p2 = exp2f(Sc[nt][2] + mv0);
            float p3 = exp2f(Sc[nt][3] + mv1);
            l0 += p0 + p1;
            l1 += p2 + p3;
            int kk = nt >> 1, hi = (nt & 1) * 2;
            pah[kk][hi]   = packbf(p0, p1);
            pah[kk][hi+1] = packbf(p2, p3);
            pal[kk][hi]   = packbf(bferr(p0), bferr(p1));
            pal[kk][hi+1] = packbf(bferr(p2), bferr(p3));
        }

        #pragma unroll
        for (int kk = 0; kk < 4; kk++) {
            const unsigned kob = kk*32;
            #pragma unroll
            for (int pp = 0; pp < 2; pp++) {
                unsigned vbh0[4], vbl0[4], vbh1[4], vbl1[4];
                ldsm4(sb + 2*APL + kvoff[pp*2]   + kob, vbh0);
                ldsm4(sb + 3*APL + kvoff[pp*2]   + kob, vbl0);
                ldsm4(sb + 2*APL + kvoff[pp*2+1] + kob, vbh1);
                ldsm4(sb + 3*APL + kvoff[pp*2+1] + kob, vbl1);
                #pragma unroll
                for (int pl = 0; pl < 3; pl++) {
                    const unsigned* ap = (pl == 2) ? pal[kk] : pah[kk];
                    const unsigned* b0 = (pl == 1) ? vbl0 : vbh0;
                    const unsigned* b1 = (pl == 1) ? vbl1 : vbh1;
                    #pragma unroll
                    for (int hf = 0; hf < 2; hf++) {
                        mma16816(O[pp*4 + hf],     ap, b0 + hf*2);
                        mma16816(O[pp*4 + 2 + hf], ap, b1 + hf*2);
                    }
                }
            }
        }

        if (kt + 2 < Ss/64) {
            const int kn = kt + 2;
            unsigned sb2 = sbase + (unsigned)(kn % 3) * AST;
            #pragma unroll
            for (int i = 0; i < 2; i++) {
                cp16(sb2 + drow + i*16,         pKh + (size_t)kn*64*Dd + i*8);
                cp16(sb2 + APL + drow + i*16,   pKl + (size_t)kn*64*Dd + i*8);
                cp16(sb2 + 2*APL + drow + i*16, pVh + kn*64 + i*8);
                cp16(sb2 + 3*APL + drow + i*16, pVl + kn*64 + i*8);
            }
        }
        CP_COMMIT();
    }

    #pragma unroll
    for (int off = 1; off < 4; off <<= 1) {
        l0 += __shfl_xor_sync(0xffffffffu, l0, off);
        l1 += __shfl_xor_sync(0xffffffffu, l1, off);
    }
    const float inv0 = 1.0f / l0, inv1 = 1.0f / l1;

    const int q = q0 + w*16 + g;
    size_t base0 = ((size_t)b * Ss + q) * Ee + h*64;
    size_t base1 = ((size_t)b * Ss + q + 8) * Ee + h*64;
    #pragma unroll
    for (int nt = 0; nt < 8; nt++) {
        int c = nt*8 + t*2;
        float v0 = O[nt][0] * inv0, v1 = O[nt][1] * inv0;
        float v2 = O[nt][2] * inv1, v3 = O[nt][3] * inv1;
        *(unsigned*)&g_ao_h[base0 + c] = packbf(v0, v1);
        *(unsigned*)&g_ao_l[base0 + c] = packbf(bferr(v0), bferr(v1));
        *(unsigned*)&g_ao_h[base1 + c] = packbf(v2, v3);
        *(unsigned*)&g_ao_l[base1 + c] = packbf(bferr(v2), bferr(v3));
    }
}

extern "C" void kernel_launch(void* const* d_in, const int* in_sizes, int n_in,
                              void* d_out, int out_size)
{
    const float* q  = (const float*)d_in[0];
    const float* k  = (const float*)d_in[1];
    const float* v  = (const float*)d_in[2];
    const unsigned char* mask = (const unsigned char*)d_in[3];
    const float* Wq = (const float*)d_in[4];
    const float* bq = (const float*)d_in[5];
    const float* Wk = (const float*)d_in[6];
    const float* bk = (const float*)d_in[7];
    const float* Wv = (const float*)d_in[8];
    const float* bv = (const float*)d_in[9];
    const float* Wo = (const float*)d_in[10];
    const float* bo = (const float*)d_in[11];
    float* out = (float*)d_out;

    cudaFuncSetAttribute(qkv_mma,   cudaFuncAttributeMaxDynamicSharedMemorySize, GE_DYN);
    cudaFuncSetAttribute(oproj_mma, cudaFuncAttributeMaxDynamicSharedMemorySize, GE_DYN);
    cudaFuncSetAttribute(attn_mma,  cudaFuncAttributeMaxDynamicSharedMemorySize, AT_DYN);

    dim3 gc((Mrows*Ee/4 + 255)/256, 1, 7);
    conv_hilo<<<gc, 256>>>(q, k, v, Wq, Wk, Wv, Wo);

    dim3 g1(Ee/128, Mrows/128, 3);
    qkv_mma<<<g1, 256, GE_DYN>>>(bq, bk, bv);

    dim3 g2(Ss/128, Bb*Hh);
    attn_mma<<<g2, 256, AT_DYN>>>(mask);

    dim3 g3(Ee/128, Mrows/128);
    oproj_mma<<<g3, 256, GE_DYN>>>(q, bo, out);
}

// round 12
// speedup vs baseline: 2.3961x; 2.3961x over previous
// MultiHead fused block R12: SINGLE fp16 mma.sync (was bf16x3 = 3 MMAs/tile).
// At the mma.sync issue ceiling the only lever is fewer MMAs; fp16 error
// (~3e-4) fits the 1e-3 budget. cp.async double-buffered GEMM, 3-stage attn.
#include <cuda_runtime.h>
#include <cuda_fp16.h>

#define Bb 2
#define Ss 2048
#define Ee 1024
#define Hh 16
#define Dd 64
#define Mrows (Bb*Ss)
#define NHD ((size_t)Bb*Hh*Ss*Dd)

__device__ __half cA[3*(size_t)Mrows*Ee];
__device__ __half cW[4*(size_t)Ee*Ee];
__device__ __half g_qh[NHD];                 // [B,H,S,D], pre-scaled
__device__ __half g_kh[NHD];                 // [B,H,S,D]
__device__ __half g_vt[NHD];                 // [B,H,D,S]
__device__ __half g_ao[(size_t)Mrows*Ee];    // [B,S,E]

__device__ __forceinline__ unsigned smem_u32(const void* p){
    unsigned a;
    asm("{ .reg .u64 t; cvta.to.shared.u64 t, %1; cvt.u32.u64 %0, t; }"
        : "=r"(a) : "l"(p));
    return a;
}
__device__ __forceinline__ unsigned packhf(float e0, float e1){
    unsigned r;   // lo half = e0, hi half = e1
    asm("cvt.rn.f16x2.f32 %0, %1, %2;" : "=r"(r) : "f"(e1), "f"(e0));
    return r;
}
__device__ __forceinline__ void mma16816(float* d, const unsigned* a, const unsigned* b){
    asm volatile(
        "mma.sync.aligned.m16n8k16.row.col.f32.f16.f16.f32 "
        "{%0,%1,%2,%3}, {%4,%5,%6,%7}, {%8,%9}, {%0,%1,%2,%3};"
        : "+f"(d[0]), "+f"(d[1]), "+f"(d[2]), "+f"(d[3])
        : "r"(a[0]), "r"(a[1]), "r"(a[2]), "r"(a[3]), "r"(b[0]), "r"(b[1]));
}
__device__ __forceinline__ void ldsm4(unsigned addr, unsigned* r){
    asm volatile("ldmatrix.sync.aligned.m8n8.x4.shared.b16 {%0,%1,%2,%3}, [%4];"
                 : "=r"(r[0]), "=r"(r[1]), "=r"(r[2]), "=r"(r[3]) : "r"(addr));
}
__device__ __forceinline__ void cp16(unsigned dst, const void* src){
    asm volatile("cp.async.cg.shared.global [%0], [%1], 16;"
                 :: "r"(dst), "l"(__cvta_generic_to_global(src)) : "memory");
}
#define CP_COMMIT() asm volatile("cp.async.commit_group;" ::: "memory")
#define CP_WAIT(n)  asm volatile("cp.async.wait_group %0;" :: "n"(n) : "memory")

// ---------------------------------------------------------------------------
// Convert fp32 -> fp16 planes. z=0..2 inputs, z=3..6 weights.
// ---------------------------------------------------------------------------
__global__ __launch_bounds__(256) void conv_h(
    const float* __restrict__ q, const float* __restrict__ k,
    const float* __restrict__ v,
    const float* __restrict__ Wq, const float* __restrict__ Wk,
    const float* __restrict__ Wv, const float* __restrict__ Wo)
{
    const int z = blockIdx.z;
    const float* src; __half* dh; size_t n;
    if (z < 3) {
        src = (z == 0) ? q : (z == 1) ? k : v;
        dh = cA + (size_t)z * Mrows * Ee;
        n = (size_t)Mrows * Ee;
    } else {
        src = (z == 3) ? Wq : (z == 4) ? Wk : (z == 5) ? Wv : Wo;
        dh = cW + (size_t)(z - 3) * Ee * Ee;
        n = (size_t)Ee * Ee;
    }
    size_t i = ((size_t)blockIdx.x * 256 + threadIdx.x) * 4;
    if (i >= n) return;
    float4 x = *(const float4*)(src + i);
    *(unsigned*)&dh[i]   = packhf(x.x, x.y);
    *(unsigned*)&dh[i+2] = packhf(x.z, x.w);
}

// ---------------------------------------------------------------------------
// GEMM core: 128x128 CTA, BK=32, double-buffered cp.async, 256 threads,
// 8 warps (4m x 2n), warp tile 32x64, single fp16. Row stride 80B (64B data).
// ---------------------------------------------------------------------------
#define GPL 10240              // plane: 128 rows * 80B
#define GST (2*GPL)            // stage (A+B): 20480
#define GE_DYN (2*GST)         // 40960

__device__ __forceinline__ void gemm_tc(float acc[2][8][4],
        const __half* __restrict__ Ag, const __half* __restrict__ Bg,
        unsigned sbase, int tid)
{
    const int lane = tid & 31, wid = tid >> 5;
    const int wm = (wid & 3) * 32, wn = (wid >> 2) * 64;

    const int r = tid >> 1, ch = tid & 1;      // row 0..127, 32B half-row
    const __half* pA = Ag + (size_t)r * Ee + ch * 16;
    const __half* pB = Bg + (size_t)r * Ee + ch * 16;
    const unsigned drow = (unsigned)(r * 80 + ch * 32);

    unsigned aoff[2];
    #pragma unroll
    for (int mt = 0; mt < 2; mt++) {
        int row = wm + mt*16 + ((lane>>3)&1)*8 + (lane&7);
        aoff[mt] = (unsigned)(row*80 + ((lane>>4)<<4));
    }
    unsigned boff[4];
    #pragma unroll
    for (int np = 0; np < 4; np++) {
        int row = wn + np*16 + ((lane>>4)&1)*8 + (lane&7);
        boff[np] = (unsigned)(row*80 + (((lane>>3)&1)<<4));
    }

    // prologue: stage 0
    {
        unsigned sb = sbase;
        cp16(sb + drow,            pA);
        cp16(sb + drow + 16,       pA + 8);
        cp16(sb + GPL + drow,      pB);
        cp16(sb + GPL + drow + 16, pB + 8);
        CP_COMMIT();
    }

    for (int s = 0; s < Ee/32; s++) {
        CP_WAIT(0);
        __syncthreads();
        const unsigned sb = sbase + (unsigned)(s & 1) * GST;

        if (s + 1 < Ee/32) {
            const int k0 = (s + 1) * 32;
            unsigned sb2 = sbase + (unsigned)((s + 1) & 1) * GST;
            cp16(sb2 + drow,            pA + k0);
            cp16(sb2 + drow + 16,       pA + k0 + 8);
            cp16(sb2 + GPL + drow,      pB + k0);
            cp16(sb2 + GPL + drow + 16, pB + k0 + 8);
        }
        CP_COMMIT();

        #pragma unroll
        for (int kh = 0; kh < 2; kh++) {
            const unsigned kob = kh * 32;
            unsigned a0[4], a1[4];
            ldsm4(sb + aoff[0] + kob, a0);
            ldsm4(sb + aoff[1] + kob, a1);
            #pragma unroll
            for (int np = 0; np < 4; np++) {
                unsigned bb[4];
                ldsm4(sb + GPL + boff[np] + kob, bb);
                #pragma unroll
                for (int hf = 0; hf < 2; hf++) {
                    mma16816(acc[0][np*2+hf], a0, bb + hf*2);
                    mma16816(acc[1][np*2+hf], a1, bb + hf*2);
                }
            }
        }
    }
}

// ---------------------------------------------------------------------------
// QKV projection; writes fp16 planes (Q pre-scaled by 0.125*log2e).
// ---------------------------------------------------------------------------
__global__ __launch_bounds__(256, 2) void qkv_mma(
    const float* __restrict__ bq, const float* __restrict__ bk,
    const float* __restrict__ bv)
{
    extern __shared__ char smraw[];
    unsigned sbase = smem_u32(smraw);
    const int tid = threadIdx.x;
    const int z = blockIdx.z;
    const int m0 = blockIdx.y * 128, n0 = blockIdx.x * 128;
    const float* bias = (z == 0) ? bq : (z == 1) ? bk : bv;

    float acc[2][8][4] = {};
    gemm_tc(acc,
            cA + ((size_t)z*Mrows + m0)*Ee,
            cW + ((size_t)z*Ee + n0)*Ee,
            sbase, tid);

    const int lane = tid & 31, wid = tid >> 5;
    const int g = lane >> 2, t = lane & 3;
    const int wm = (wid & 3) * 32, wn = (wid >> 2) * 64;
    const float QSCALE = 0.125f * 1.4426950408889634f;

    #pragma unroll
    for (int mt = 0; mt < 2; mt++) {
        #pragma unroll
        for (int nt = 0; nt < 8; nt++) {
            int m = m0 + wm + mt*16 + g;
            int n = n0 + wn + nt*8 + t*2;
            float b0v = bias[n], b1v = bias[n+1];
            int b = m >> 11, s = m & 2047;
            int h = n >> 6, d = n & 63;
            float v00 = acc[mt][nt][0] + b0v, v01 = acc[mt][nt][1] + b1v;
            float v10 = acc[mt][nt][2] + b0v, v11 = acc[mt][nt][3] + b1v;
            if (z == 0) {
                v00 *= QSCALE; v01 *= QSCALE; v10 *= QSCALE; v11 *= QSCALE;
                size_t i0 = (((size_t)(b*Hh + h))*Ss + s)*Dd + d;
                *(unsigned*)&g_qh[i0]        = packhf(v00, v01);
                *(unsigned*)&g_qh[i0 + 8*Dd] = packhf(v10, v11);
            } else if (z == 1) {
                size_t i0 = (((size_t)(b*Hh + h))*Ss + s)*Dd + d;
                *(unsigned*)&g_kh[i0]        = packhf(v00, v01);
                *(unsigned*)&g_kh[i0 + 8*Dd] = packhf(v10, v11);
            } else {
                size_t i0 = (((size_t)(b*Hh + h))*Dd + d)*Ss + s;
                g_vt[i0]      = __float2half_rn(v00);
                g_vt[i0+Ss]   = __float2half_rn(v01);
                g_vt[i0+8]    = __float2half_rn(v10);
                g_vt[i0+Ss+8] = __float2half_rn(v11);
            }
        }
    }
}

// ---------------------------------------------------------------------------
// Output projection + bias + residual (fp32 out)
// ---------------------------------------------------------------------------
__global__ __launch_bounds__(256, 2) void oproj_mma(
    const float* __restrict__ qin, const float* __restrict__ bo,
    float* __restrict__ out)
{
    extern __shared__ char smraw[];
    unsigned sbase = smem_u32(smraw);
    const int tid = threadIdx.x;
    const int m0 = blockIdx.y * 128, n0 = blockIdx.x * 128;

    float acc[2][8][4] = {};
    gemm_tc(acc,
            g_ao + (size_t)m0*Ee,
            cW + ((size_t)3*Ee + n0)*Ee,
            sbase, tid);

    const int lane = tid & 31, wid = tid >> 5;
    const int g = lane >> 2, t = lane & 3;
    const int wm = (wid & 3) * 32, wn = (wid >> 2) * 64;

    #pragma unroll
    for (int mt = 0; mt < 2; mt++) {
        #pragma unroll
        for (int nt = 0; nt < 8; nt++) {
            int m = m0 + wm + mt*16 + g;
            int n = n0 + wn + nt*8 + t*2;
            float b0v = bo[n], b1v = bo[n+1];
            size_t i0 = (size_t)m * Ee + n;
            size_t i1 = (size_t)(m+8) * Ee + n;
            out[i0]   = acc[mt][nt][0] + b0v + qin[i0];
            out[i0+1] = acc[mt][nt][1] + b1v + qin[i0+1];
            out[i1]   = acc[mt][nt][2] + b0v + qin[i1];
            out[i1+1] = acc[mt][nt][3] + b1v + qin[i1+1];
        }
    }
}

// ---------------------------------------------------------------------------
// Flash attention: 3-stage cp.async K/V pipeline, no-max softmax (Q pre-
// scaled), single fp16. CTA = (b,h) x 128 queries, 256 threads.
// Smem: 2 planes (K,V) x 64 rows x 144B per stage; Q staged in stage 0.
// ---------------------------------------------------------------------------
#define APL 9216               // plane: 64 rows * 144B
#define AST (2*APL)            // stage: 18432
#define AMSK (3*AST)           // 55296
#define AT_DYN (AMSK + 2048)

__global__ __launch_bounds__(256, 2) void attn_mma(const unsigned char* __restrict__ mask)
{
    extern __shared__ char smraw[];
    unsigned sbase = smem_u32(smraw);
    const int tid = threadIdx.x;
    const int lane = tid & 31, w = tid >> 5;
    const int g = lane >> 2, t = lane & 3;
    const int bh = blockIdx.y, b = bh >> 4, h = bh & 15;
    const int q0 = blockIdx.x * 128;

    ((unsigned long long*)(smraw + AMSK))[tid] =
        ((const unsigned long long*)(mask + (size_t)b * Ss))[tid];

    // Q staging into stage 0: rows 0..63 -> plane 0, rows 64..127 -> plane 1.
    {
        const __half* Qh = g_qh + ((size_t)bh * Ss + q0) * Dd;
        const int qr = tid >> 1;
        const int qc = (tid & 1) * 4;
        const unsigned hiplane = (qr >= 64) ? (unsigned)APL : 0u;
        unsigned qdst = sbase + hiplane + (unsigned)((qr & 63) * 144 + qc * 16);
        #pragma unroll
        for (int i = 0; i < 4; i++)
            cp16(qdst + i*16, Qh + (size_t)qr*64 + (qc+i)*8);
        CP_COMMIT();
        CP_WAIT(0);
        __syncthreads();
    }

    unsigned qf[4][4];
    {
        const int rowfull = w*16 + ((lane>>3)&1)*8 + (lane&7);
        const unsigned hiplane = (rowfull >= 64) ? (unsigned)APL : 0u;
        const unsigned off = hiplane + (unsigned)((rowfull & 63)*144 + ((lane>>4)<<4));
        #pragma unroll
        for (int dt = 0; dt < 4; dt++)
            ldsm4(sbase + off + dt*32, qf[dt]);
    }
    __syncthreads();

    const __half* Kg = g_kh + (size_t)bh * Ss * Dd;
    const __half* Vg = g_vt + (size_t)bh * Dd * Ss;

    const int r2 = tid >> 2;                 // 0..63
    const int cb = (tid & 3) * 2;            // 2 chunks of 16B
    const unsigned drow = (unsigned)(r2 * 144 + cb * 16);
    const __half* pK = Kg + (size_t)r2 * Dd + cb * 8;
    const __half* pV = Vg + (size_t)r2 * Ss + cb * 8;

    #pragma unroll
    for (int st = 0; st < 2; st++) {
        unsigned sb = sbase + st*AST;
        #pragma unroll
        for (int i = 0; i < 2; i++) {
            cp16(sb + drow + i*16,       pK + (size_t)st*64*Dd + i*8);
            cp16(sb + APL + drow + i*16, pV + st*64 + i*8);
        }
        CP_COMMIT();
    }

    unsigned kvoff[4];
    #pragma unroll
    for (int np = 0; np < 4; np++) {
        int row = np*16 + ((lane>>4)&1)*8 + (lane&7);
        kvoff[np] = (unsigned)(row*144 + (((lane>>3)&1)<<4));
    }

    const unsigned char* mb = (const unsigned char*)(smraw + AMSK);
    float O[8][4] = {};
    float l0 = 0.f, l1 = 0.f;

    for (int kt = 0; kt < Ss/64; kt++) {
        CP_WAIT(1);
        __syncthreads();
        const unsigned sb = sbase + (unsigned)(kt % 3) * AST;

        float Sc[8][4] = {};
        #pragma unroll
        for (int dt = 0; dt < 4; dt++) {
            const unsigned kob = dt*32;
            #pragma unroll
            for (int np = 0; np < 4; np++) {
                unsigned kb[4];
                ldsm4(sb + kvoff[np] + kob, kb);
                #pragma unroll
                for (int hf = 0; hf < 2; hf++)
                    mma16816(Sc[np*2+hf], qf[dt], kb + hf*2);
            }
        }

        unsigned pa[4][4];
        #pragma unroll
        for (int nt = 0; nt < 8; nt++) {
            int j = kt*64 + nt*8 + t*2;
            float mv0 = mb[j]   ? -1e9f : 0.f;
            float mv1 = mb[j+1] ? -1e9f : 0.f;
            float p0 = exp2f(Sc[nt][0] + mv0);
            float p1 = exp2f(Sc[nt][1] + mv1);
            float p2 = exp2f(Sc[nt][2] + mv0);
            float p3 = exp2f(Sc[nt][3] + mv1);
            l0 += p0 + p1;
            l1 += p2 + p3;
            int kk = nt >> 1, hi = (nt & 1) * 2;
            pa[kk][hi]   = packhf(p0, p1);
            pa[kk][hi+1] = packhf(p2, p3);
        }

        #pragma unroll
        for (int kk = 0; kk < 4; kk++) {
            const unsigned kob = kk*32;
            #pragma unroll
            for (int np = 0; np < 4; np++) {
                unsigned vb[4];
                ldsm4(sb + APL + kvoff[np] + kob, vb);
                #pragma unroll
                for (int hf = 0; hf < 2; hf++)
                    mma16816(O[np*2+hf], pa[kk], vb + hf*2);
            }
        }

        if (kt + 2 < Ss/64) {
            const int kn = kt + 2;
            unsigned sb2 = sbase + (unsigned)(kn % 3) * AST;
            #pragma unroll
            for (int i = 0; i < 2; i++) {
                cp16(sb2 + drow + i*16,       pK + (size_t)kn*64*Dd + i*8);
                cp16(sb2 + APL + drow + i*16, pV + kn*64 + i*8);
            }
        }
        CP_COMMIT();
    }

    #pragma unroll
    for (int off = 1; off < 4; off <<= 1) {
        l0 += __shfl_xor_sync(0xffffffffu, l0, off);
        l1 += __shfl_xor_sync(0xffffffffu, l1, off);
    }
    const float inv0 = 1.0f / l0, inv1 = 1.0f / l1;

    const int q = q0 + w*16 + g;
    size_t base0 = ((size_t)b * Ss + q) * Ee + h*64;
    size_t base1 = ((size_t)b * Ss + q + 8) * Ee + h*64;
    #pragma unroll
    for (int nt = 0; nt < 8; nt++) {
        int c = nt*8 + t*2;
        *(unsigned*)&g_ao[base0 + c] = packhf(O[nt][0] * inv0, O[nt][1] * inv0);
        *(unsigned*)&g_ao[base1 + c] = packhf(O[nt][2] * inv1, O[nt][3] * inv1);
    }
}

extern "C" void kernel_launch(void* const* d_in, const int* in_sizes, int n_in,
                              void* d_out, int out_size)
{
    const float* q  = (const float*)d_in[0];
    const float* k  = (const float*)d_in[1];
    const float* v  = (const float*)d_in[2];
    const unsigned char* mask = (const unsigned char*)d_in[3];
    const float* Wq = (const float*)d_in[4];
    const float* bq = (const float*)d_in[5];
    const float* Wk = (const float*)d_in[6];
    const float* bk = (const float*)d_in[7];
    const float* Wv = (const float*)d_in[8];
    const float* bv = (const float*)d_in[9];
    const float* Wo = (const float*)d_in[10];
    const float* bo = (const float*)d_in[11];
    float* out = (float*)d_out;

    cudaFuncSetAttribute(qkv_mma,   cudaFuncAttributeMaxDynamicSharedMemorySize, GE_DYN);
    cudaFuncSetAttribute(oproj_mma, cudaFuncAttributeMaxDynamicSharedMemorySize, GE_DYN);
    cudaFuncSetAttribute(attn_mma,  cudaFuncAttributeMaxDynamicSharedMemorySize, AT_DYN);

    dim3 gc((Mrows*Ee/4 + 255)/256, 1, 7);
    conv_h<<<gc, 256>>>(q, k, v, Wq, Wk, Wv, Wo);

    dim3 g1(Ee/128, Mrows/128, 3);
    qkv_mma<<<g1, 256, GE_DYN>>>(bq, bk, bv);

    dim3 g2(Ss/128, Bb*Hh);
    attn_mma<<<g2, 256, AT_DYN>>>(mask);

    dim3 g3(Ee/128, Mrows/128);
    oproj_mma<<<g3, 256, GE_DYN>>>(q, bo, out);
}